// round 12
// baseline (speedup 1.0000x reference)
#include <cuda_runtime.h>
#include <cuda_bf16.h>
#include <cstdint>
#include <math.h>

// ---------------- static scratch ----------------
__device__ __align__(16) int8_t g_A8h[102760448];  // 8192x12544
__device__ __align__(16) int8_t g_A8l[102760448];
__device__ __align__(16) int8_t g_W8h[25690112];   // [w1;w3] 2048x12544
__device__ __align__(16) int8_t g_W8l[25690112];
__device__ float g_sA[8192];
__device__ float g_sW[2048];
__device__ __align__(16) __nv_bfloat16 g_w24_hi[2097152];   // [w2;w4] 2048x1024
__device__ __align__(16) __nv_bfloat16 g_w24_lo[2097152];
__device__ __align__(16) __nv_bfloat16 g_act1_hi[16777216]; // 8192x2048
__device__ __align__(16) __nv_bfloat16 g_act1_lo[16777216];
__device__ __align__(16) float         g_act2[16777216];
__device__ __align__(16) float         g_heads[524288];

// ---------------- helpers ----------------
__device__ __forceinline__ uint32_t smem_u32(const void* p) {
    uint32_t a;
    asm("{ .reg .u64 t; cvta.to.shared.u64 t, %1; cvt.u32.u64 %0, t; }" : "=r"(a) : "l"(p));
    return a;
}
__device__ __forceinline__ uint32_t swz128(uint32_t x) { return x ^ ((x >> 3) & 0x70); }
__device__ __forceinline__ uint32_t swz64(uint32_t x)  { return x ^ ((x >> 3) & 0x30); }

__device__ __forceinline__ void cp16(uint32_t dst, const void* src) {
    asm volatile("cp.async.cg.shared.global [%0], [%1], 16;"
                 :: "r"(dst), "l"(__cvta_generic_to_global(src)) : "memory");
}
#define CP_COMMIT() asm volatile("cp.async.commit_group;" ::: "memory")
#define CP_WAIT1()  asm volatile("cp.async.wait_group 1;" ::: "memory")

__device__ __forceinline__ void ldsm4(uint32_t* r, uint32_t a) {
    asm volatile("ldmatrix.sync.aligned.m8n8.x4.shared.b16 {%0,%1,%2,%3}, [%4];"
                 : "=r"(r[0]), "=r"(r[1]), "=r"(r[2]), "=r"(r[3]) : "r"(a));
}
__device__ __forceinline__ void mma16816(float* d, const uint32_t* a, uint32_t b0, uint32_t b1) {
    asm volatile(
        "mma.sync.aligned.m16n8k16.row.col.f32.bf16.bf16.f32 "
        "{%0,%1,%2,%3}, {%4,%5,%6,%7}, {%8,%9}, {%0,%1,%2,%3};"
        : "+f"(d[0]), "+f"(d[1]), "+f"(d[2]), "+f"(d[3])
        : "r"(a[0]), "r"(a[1]), "r"(a[2]), "r"(a[3]), "r"(b0), "r"(b1));
}
__device__ __forceinline__ void imma16832(int* d, const uint32_t* a, uint32_t b0, uint32_t b1) {
    asm volatile(
        "mma.sync.aligned.m16n8k32.row.col.s32.s8.s8.s32 "
        "{%0,%1,%2,%3}, {%4,%5,%6,%7}, {%8,%9}, {%0,%1,%2,%3};"
        : "+r"(d[0]), "+r"(d[1]), "+r"(d[2]), "+r"(d[3])
        : "r"(a[0]), "r"(a[1]), "r"(a[2]), "r"(a[3]), "r"(b0), "r"(b1));
}
__device__ __forceinline__ uint32_t bf2u(__nv_bfloat16 a, __nv_bfloat16 b) {
    __nv_bfloat162 t; t.x = a; t.y = b;
    return *reinterpret_cast<uint32_t*>(&t);
}

// ============ GEMM1 int8: CTA 128x128, 8 warps, warp 64x32 ============
static constexpr int STG1 = 32768;              // Ah 8K | Al 8K | Bh 8K | Bl 8K
static constexpr int SMEM1 = 2 * STG1;          // 64KB
static constexpr int K1 = 12544;

__global__ void __launch_bounds__(256, 1) gemm1_int8(
    const float* __restrict__ b1, const float* __restrict__ b3)
{
    extern __shared__ char smem[];
    const uint32_t sbase = smem_u32(smem);
    const int tid = threadIdx.x, wid = tid >> 5, lid = tid & 31;
    const int n_base = blockIdx.x * 128;
    const int m_base = blockIdx.y * 128;
    const float* bias = (n_base >= 1024) ? b3 : b1;

    const int m0 = (wid & 1) * 64, n0 = (wid >> 1) * 32;
    const int lrow = lid & 15;
    const int lcolB = (lid >> 4) * 16;
    const int ld_r = tid >> 2, ld_c = tid & 3;   // 64 rows per pass, 2 passes

    int acc1[4][4][4], acc2[4][4][4];
#pragma unroll
    for (int mt = 0; mt < 4; ++mt)
#pragma unroll
        for (int j = 0; j < 4; ++j)
#pragma unroll
            for (int q = 0; q < 4; ++q) { acc1[mt][j][q] = 0; acc2[mt][j][q] = 0; }

    const int NS = K1 >> 6;
    auto load_stage = [&](int s) {
        if (s < NS) {
            const size_t kb = (size_t)s * 64;
            const uint32_t so = sbase + (uint32_t)(s & 1) * STG1;
#pragma unroll
            for (int i = 0; i < 2; ++i) {                    // FIX: cover rows 0..127
                const int row = ld_r + i * 64;
                const uint32_t sw = swz64((uint32_t)(row * 64 + ld_c * 16));
                const size_t ga = (size_t)(m_base + row) * K1 + kb + ld_c * 16;
                const size_t gb = (size_t)(n_base + row) * K1 + kb + ld_c * 16;
                cp16(so + sw,         g_A8h + ga);
                cp16(so + 8192 + sw,  g_A8l + ga);
                cp16(so + 16384 + sw, g_W8h + gb);
                cp16(so + 24576 + sw, g_W8l + gb);
            }
        }
        CP_COMMIT();
    };

    load_stage(0);

#pragma unroll 1
    for (int s = 0; s < NS; ++s) {
        load_stage(s + 1);
        CP_WAIT1();
        __syncthreads();
        const uint32_t so = sbase + (uint32_t)(s & 1) * STG1;
#pragma unroll
        for (int kk = 0; kk < 2; ++kk) {
            uint32_t ah[4][4], al[4][4];
#pragma unroll
            for (int mt = 0; mt < 4; ++mt) {
                const uint32_t off = swz64((uint32_t)((m0 + mt * 16 + lrow) * 64 + kk * 32 + lcolB));
                ldsm4(ah[mt], so + off);
                ldsm4(al[mt], so + 8192 + off);
            }
#pragma unroll
            for (int j2 = 0; j2 < 2; ++j2) {
                uint32_t bh[4], bl[4];
                const uint32_t off = swz64((uint32_t)((n0 + j2 * 16 + lrow) * 64 + kk * 32 + lcolB));
                ldsm4(bh, so + 16384 + off);
                ldsm4(bl, so + 24576 + off);
#pragma unroll
                for (int mt = 0; mt < 4; ++mt)
#pragma unroll
                    for (int h = 0; h < 2; ++h) {
                        imma16832(acc1[mt][j2 * 2 + h], ah[mt], bh[h], bh[2 + h]);
                        imma16832(acc2[mt][j2 * 2 + h], ah[mt], bl[h], bl[2 + h]);
                        imma16832(acc2[mt][j2 * 2 + h], al[mt], bh[h], bh[2 + h]);
                    }
            }
        }
        __syncthreads();
    }

    const int grp = lid >> 2, qd = lid & 3;
#pragma unroll
    for (int mt = 0; mt < 4; ++mt)
#pragma unroll
        for (int j = 0; j < 4; ++j) {
            const int colg = n_base + n0 + j * 8 + qd * 2;
            const int cb = colg & 1023;
            const float sb0 = g_sW[colg], sb1 = g_sW[colg + 1];
            const float bb0 = __ldg(bias + cb), bb1 = __ldg(bias + cb + 1);
#pragma unroll
            for (int ph = 0; ph < 2; ++ph) {
                const int row = m_base + m0 + mt * 16 + grp + ph * 8;
                const float sa = g_sA[row];
                float v0 = fmaxf(sa * sb0 * ((float)acc1[mt][j][2 * ph]     +
                                             (float)acc2[mt][j][2 * ph]     * (1.0f / 256.0f)) + bb0, 0.f);
                float v1 = fmaxf(sa * sb1 * ((float)acc1[mt][j][2 * ph + 1] +
                                             (float)acc2[mt][j][2 * ph + 1] * (1.0f / 256.0f)) + bb1, 0.f);
                __nv_bfloat16 h0 = __float2bfloat16_rn(v0), h1 = __float2bfloat16_rn(v1);
                const size_t o = (size_t)row * 2048 + colg;
                *reinterpret_cast<uint32_t*>(g_act1_hi + o) = bf2u(h0, h1);
                *reinterpret_cast<uint32_t*>(g_act1_lo + o) =
                    bf2u(__float2bfloat16_rn(v0 - __bfloat162float(h0)),
                         __float2bfloat16_rn(v1 - __bfloat162float(h1)));
            }
        }
}

// ============ GEMM2 (bf16x3): CTA 128x256 ============
static constexpr int STG2 = 98304;
static constexpr int SMEM2 = 2 * STG2;

__global__ void __launch_bounds__(256, 1) gemm2_kernel(
    const float* __restrict__ biasA, const float* __restrict__ biasB)
{
    extern __shared__ char smem[];
    const uint32_t sbase = smem_u32(smem);
    const int tid = threadIdx.x, wid = tid >> 5, lid = tid & 31;
    const int n_base = blockIdx.x * 256;
    const int m_base = blockIdx.y * 128;
    const int a_off = (n_base >= 1024) ? 1024 : 0;
    const float* bias = (n_base >= 1024) ? biasB : biasA;
    const int K = 1024, ldA = 2048, NS = 16;

    const int m0 = (wid & 1) * 64, n0 = (wid >> 1) * 64;
    const int lrow = lid & 15, lcol = (lid >> 4) * 16;
    const int ld_r0 = tid >> 3, ld_c = tid & 7;

    float acc[4][8][4];
#pragma unroll
    for (int mt = 0; mt < 4; ++mt)
#pragma unroll
        for (int j = 0; j < 8; ++j)
#pragma unroll
            for (int q = 0; q < 4; ++q) acc[mt][j][q] = 0.f;

    auto load_stage = [&](int s) {
        if (s < NS) {
            const size_t kb = (size_t)s * 64;
            const uint32_t so = sbase + (uint32_t)(s & 1) * STG2;
#pragma unroll
            for (int i = 0; i < 4; ++i) {
                const int row = ld_r0 + i * 32;
                const uint32_t sw = swz128((uint32_t)(row * 128 + ld_c * 16));
                const size_t ga = (size_t)(m_base + row) * ldA + a_off + kb + ld_c * 8;
                cp16(so + sw,         g_act1_hi + ga);
                cp16(so + 16384 + sw, g_act1_lo + ga);
            }
#pragma unroll
            for (int i = 0; i < 8; ++i) {
                const int row = ld_r0 + i * 32;
                const uint32_t sw = swz128((uint32_t)(row * 128 + ld_c * 16));
                const size_t gb = (size_t)(n_base + row) * K + kb + ld_c * 8;
                cp16(so + 32768 + sw, g_w24_hi + gb);
                cp16(so + 65536 + sw, g_w24_lo + gb);
            }
        }
        CP_COMMIT();
    };

    load_stage(0);
#pragma unroll 1
    for (int s = 0; s < NS; ++s) {
        load_stage(s + 1);
        CP_WAIT1();
        __syncthreads();
        const uint32_t so = sbase + (uint32_t)(s & 1) * STG2;
#pragma unroll
        for (int kk = 0; kk < 4; ++kk) {
            const int kb2 = kk * 32;
            uint32_t af[4][2][4];
#pragma unroll
            for (int mt = 0; mt < 4; ++mt) {
                const uint32_t off = swz128((uint32_t)((m0 + mt * 16 + lrow) * 128 + kb2 + lcol));
                ldsm4(af[mt][0], so + off);
                ldsm4(af[mt][1], so + 16384 + off);
            }
#pragma unroll
            for (int j2 = 0; j2 < 4; ++j2) {
                uint32_t bh[4], bl[4];
                const uint32_t off = swz128((uint32_t)((n0 + j2 * 16 + lrow) * 128 + kb2 + lcol));
                ldsm4(bh, so + 32768 + off);
                ldsm4(bl, so + 65536 + off);
#pragma unroll
                for (int mt = 0; mt < 4; ++mt)
#pragma unroll
                    for (int h = 0; h < 2; ++h) {
                        float* d = acc[mt][j2 * 2 + h];
                        mma16816(d, af[mt][0], bh[h], bh[2 + h]);
                        mma16816(d, af[mt][0], bl[h], bl[2 + h]);
                        mma16816(d, af[mt][1], bh[h], bh[2 + h]);
                    }
            }
        }
        __syncthreads();
    }

    const int grp = lid >> 2, qd = lid & 3;
#pragma unroll
    for (int mt = 0; mt < 4; ++mt)
#pragma unroll
        for (int j = 0; j < 8; ++j)
#pragma unroll
            for (int h = 0; h < 2; ++h) {
                const int row = m_base + m0 + mt * 16 + grp + h * 8;
                const int colg = n_base + n0 + (j >> 1) * 16 + (j & 1) * 8 + qd * 2;
                const int cb = colg & 1023;
                float v0 = fmaxf(acc[mt][j][2 * h]     + __ldg(bias + cb), 0.f);
                float v1 = fmaxf(acc[mt][j][2 * h + 1] + __ldg(bias + cb + 1), 0.f);
                float2 f; f.x = v0; f.y = v1;
                *reinterpret_cast<float2*>(g_act2 + (size_t)row * 2048 + colg) = f;
            }
}

// ============ prep kernels ============
__global__ void __launch_bounds__(256) rowmax_A(const float* __restrict__ s) {
    __shared__ float red[256];
    const int row = blockIdx.x;
    const float* p = s + (size_t)row * 12544;
    float m = 0.f;
    for (int k = threadIdx.x; k < 12544; k += 256) m = fmaxf(m, fabsf(p[k]));
    red[threadIdx.x] = m;
    __syncthreads();
    for (int d = 128; d; d >>= 1) {
        if (threadIdx.x < d) red[threadIdx.x] = fmaxf(red[threadIdx.x], red[threadIdx.x + d]);
        __syncthreads();
    }
    if (threadIdx.x == 0) g_sA[row] = fmaxf(red[0], 1e-30f) * (1.0f / 126.0f);
}
__global__ void __launch_bounds__(256) rowmax_W(const float* __restrict__ w1,
                                               const float* __restrict__ w3) {
    __shared__ float red[256];
    const int row = blockIdx.x;
    const float* p = (row < 1024) ? w1 + (size_t)row * 12544
                                  : w3 + (size_t)(row - 1024) * 12544;
    float m = 0.f;
    for (int k = threadIdx.x; k < 12544; k += 256) m = fmaxf(m, fabsf(p[k]));
    red[threadIdx.x] = m;
    __syncthreads();
    for (int d = 128; d; d >>= 1) {
        if (threadIdx.x < d) red[threadIdx.x] = fmaxf(red[threadIdx.x], red[threadIdx.x + d]);
        __syncthreads();
    }
    if (threadIdx.x == 0) g_sW[row] = fmaxf(red[0], 1e-30f) * (1.0f / 126.0f);
}

__device__ __forceinline__ void quant2(float v, float sinv, int8_t& h, int8_t& l) {
    float x = v * sinv;
    float hf = rintf(x);
    int lo = __float2int_rn((x - hf) * 256.0f);
    lo = max(-127, min(127, lo));
    h = (int8_t)(int)hf;
    l = (int8_t)lo;
}
__global__ void __launch_bounds__(256) quant_A(const float* __restrict__ s) {
    const size_t i4 = (size_t)blockIdx.x * 256 + threadIdx.x;
    const int row = (int)((i4 * 4) / 12544);
    const float sinv = 1.0f / g_sA[row];
    float4 v = reinterpret_cast<const float4*>(s)[i4];
    char4 hc, lc;
    quant2(v.x, sinv, (int8_t&)hc.x, (int8_t&)lc.x);
    quant2(v.y, sinv, (int8_t&)hc.y, (int8_t&)lc.y);
    quant2(v.z, sinv, (int8_t&)hc.z, (int8_t&)lc.z);
    quant2(v.w, sinv, (int8_t&)hc.w, (int8_t&)lc.w);
    reinterpret_cast<char4*>(g_A8h)[i4] = hc;
    reinterpret_cast<char4*>(g_A8l)[i4] = lc;
}
__global__ void __launch_bounds__(256) quant_W(const float* __restrict__ w1,
                                               const float* __restrict__ w3) {
    const size_t i4 = (size_t)blockIdx.x * 256 + threadIdx.x;
    const size_t half = 3211264;
    const float* src = (i4 < half) ? w1 : w3;
    const size_t li4 = (i4 < half) ? i4 : i4 - half;
    const int row = (int)((i4 * 4) / 12544);
    const float sinv = 1.0f / g_sW[row];
    float4 v = reinterpret_cast<const float4*>(src)[li4];
    char4 hc, lc;
    quant2(v.x, sinv, (int8_t&)hc.x, (int8_t&)lc.x);
    quant2(v.y, sinv, (int8_t&)hc.y, (int8_t&)lc.y);
    quant2(v.z, sinv, (int8_t&)hc.z, (int8_t&)lc.z);
    quant2(v.w, sinv, (int8_t&)hc.w, (int8_t&)lc.w);
    reinterpret_cast<char4*>(g_W8h)[i4] = hc;
    reinterpret_cast<char4*>(g_W8l)[i4] = lc;
}

__global__ void __launch_bounds__(256) conv_w24(const float* __restrict__ w2,
                                                const float* __restrict__ w4) {
    const size_t i = (size_t)blockIdx.x * 256 + threadIdx.x;
    const size_t half = 262144;
    const float* src = (i < half) ? w2 : w4;
    const size_t li = (i < half) ? i : i - half;
    float4 v = reinterpret_cast<const float4*>(src)[li];
    __nv_bfloat16 h0 = __float2bfloat16_rn(v.x), h1 = __float2bfloat16_rn(v.y);
    __nv_bfloat16 h2 = __float2bfloat16_rn(v.z), h3 = __float2bfloat16_rn(v.w);
    uint2 hp; hp.x = bf2u(h0, h1); hp.y = bf2u(h2, h3);
    reinterpret_cast<uint2*>(g_w24_hi)[i] = hp;
    uint2 lp;
    lp.x = bf2u(__float2bfloat16_rn(v.x - __bfloat162float(h0)),
                __float2bfloat16_rn(v.y - __bfloat162float(h1)));
    lp.y = bf2u(__float2bfloat16_rn(v.z - __bfloat162float(h2)),
                __float2bfloat16_rn(v.w - __bfloat162float(h3)));
    reinterpret_cast<uint2*>(g_w24_lo)[i] = lp;
}

// ============ Heads ============
__global__ void __launch_bounds__(512) heads_kernel(
    const float* __restrict__ w_cls, const float* __restrict__ b_cls,
    const float* __restrict__ w_delta, const float* __restrict__ b_delta,
    const float* __restrict__ w_pos, const float* __restrict__ b_pos,
    const float* __restrict__ w_emb, const float* __restrict__ b_emb)
{
    const int wid = threadIdx.x >> 5, lid = threadIdx.x & 31;
    const int row = blockIdx.x * 16 + wid;
#pragma unroll 1
    for (int o = 0; o < 53; ++o) {
        const float* Wp; const float* bp; int wr, ac;
        if (o < 3)       { Wp = w_cls;   bp = b_cls;   wr = o;      ac = 0; }
        else if (o < 15) { Wp = w_delta; bp = b_delta; wr = o - 3;  ac = 0; }
        else if (o < 21) { Wp = w_pos;   bp = b_pos;   wr = o - 15; ac = 0; }
        else             { Wp = w_emb;   bp = b_emb;   wr = o - 21; ac = 1024; }
        const float* a = g_act2 + (size_t)row * 2048 + ac;
        const float* w = Wp + (size_t)wr * 1024;
        float s = 0.f;
#pragma unroll 8
        for (int k = lid; k < 1024; k += 32) s += a[k] * w[k];
#pragma unroll
        for (int d = 16; d; d >>= 1) s += __shfl_xor_sync(0xFFFFFFFFu, s, d);
        if (lid == 0) g_heads[(size_t)row * 64 + o] = s + bp[wr];
    }
}

// ============ Postprocess ============
__global__ void __launch_bounds__(128) post_kernel(
    const float* __restrict__ rois, float* __restrict__ out, int out_size)
{
    const int n = blockIdx.x * blockDim.x + threadIdx.x;
    if (n >= 8192) return;
    const float* h = g_heads + (size_t)n * 64;
    float c0 = h[0], c1 = h[1], c2 = h[2];
    float m = fmaxf(c0, fmaxf(c1, c2));
    float e0 = expf(c0 - m), e1 = expf(c1 - m), e2 = expf(c2 - m);
    float inv = 1.f / (e0 + e1 + e2);
    float sc0 = e1 * inv, sc1 = e2 * inv;
    float x1 = rois[n * 5 + 1], y1 = rois[n * 5 + 2];
    float x2 = rois[n * 5 + 3], y2 = rois[n * 5 + 4];
    float bw = x2 - x1, bh = y2 - y1;
    float cx = x1 + 0.5f * bw, cy = y1 + 0.5f * bh;
#pragma unroll
    for (int j = 0; j < 2; ++j) {
        float d0 = h[7 + 4 * j] * 0.1f, d1 = h[8 + 4 * j] * 0.1f;
        float d2 = h[9 + 4 * j] * 0.2f, d3 = h[10 + 4 * j] * 0.2f;
        float p0 = h[17 + 2 * j] * 0.1f, p1 = h[18 + 2 * j] * 0.1f;
        float pcx = d0 * bw + cx, pcy = d1 * bh + cy;
        float pw = expf(d2) * bw, phh = expf(d3) * bh;
        float px = p0 * bw + cx, py = p1 * bh + cy;
        float* ob = out + (size_t)(2 * n + j) * 8;
        ob[0] = pcx - 0.5f * pw;  ob[1] = pcy - 0.5f * phh;
        ob[2] = pcx + 0.5f * pw;  ob[3] = pcy + 0.5f * phh;
        ob[4] = px; ob[5] = py;
        ob[6] = j ? sc1 : sc0;
        ob[7] = (float)(j + 1);
        float* oe = out + 131072 + (size_t)(2 * n + j) * 32;
#pragma unroll
        for (int t = 0; t < 32; ++t) oe[t] = h[21 + t];
    }
    if (n == 0 && out_size > 655360) out[655360] = 2.0f;
}

// ============ launch ============
extern "C" void kernel_launch(void* const* d_in, const int* in_sizes, int n_in,
                              void* d_out, int out_size) {
    const float* pool   = (const float*)d_in[0];
    const float* rois   = (const float*)d_in[1];
    const float* w_fc1  = (const float*)d_in[2];
    const float* b_fc1  = (const float*)d_in[3];
    const float* w_fc2  = (const float*)d_in[4];
    const float* b_fc2  = (const float*)d_in[5];
    const float* w_fc3  = (const float*)d_in[6];
    const float* b_fc3  = (const float*)d_in[7];
    const float* w_fc4  = (const float*)d_in[8];
    const float* b_fc4  = (const float*)d_in[9];
    const float* w_cls  = (const float*)d_in[10];
    const float* b_cls  = (const float*)d_in[11];
    const float* w_delta= (const float*)d_in[12];
    const float* b_delta= (const float*)d_in[13];
    const float* w_pos  = (const float*)d_in[14];
    const float* b_pos  = (const float*)d_in[15];
    const float* w_emb  = (const float*)d_in[16];
    const float* b_emb  = (const float*)d_in[17];
    float* out = (float*)d_out;

    cudaFuncSetAttribute(gemm1_int8,   cudaFuncAttributeMaxDynamicSharedMemorySize, SMEM1);
    cudaFuncSetAttribute(gemm2_kernel, cudaFuncAttributeMaxDynamicSharedMemorySize, SMEM2);

    rowmax_A<<<8192, 256>>>(pool);                   // L1
    rowmax_W<<<2048, 256>>>(w_fc1, w_fc3);           // L2
    quant_A<<<100352, 256>>>(pool);                  // L3
    quant_W<<<25088, 256>>>(w_fc1, w_fc3);           // L4
    conv_w24<<<2048, 256>>>(w_fc2, w_fc4);           // L5
    gemm1_int8<<<dim3(16, 64), 256, SMEM1>>>(b_fc1, b_fc3);   // L6 (ncu target)
    gemm2_kernel<<<dim3(8, 64), 256, SMEM2>>>(b_fc2, b_fc4);
    heads_kernel<<<512, 512>>>(w_cls, b_cls, w_delta, b_delta, w_pos, b_pos, w_emb, b_emb);
    post_kernel<<<64, 128>>>(rois, out, out_size);
}

// round 13
// speedup vs baseline: 3.6737x; 3.6737x over previous
#include <cuda_runtime.h>
#include <cuda_fp16.h>
#include <cstdint>
#include <math.h>

// ---------------- static scratch ----------------
__device__ __align__(16) __half g_A16[102760448];    // 8192x12544 fp16
__device__ __align__(16) __half g_W13h[25690112];    // [w1;w3] 2048x12544
__device__ __align__(16) __half g_W13l[25690112];
__device__ __align__(16) __half g_w24h[2097152];     // [w2;w4] 2048x1024
__device__ __align__(16) __half g_w24l[2097152];
__device__ __align__(16) __half g_act16[16777216];   // 8192x2048 fp16
__device__ __align__(16) float  g_act2[16777216];
__device__ __align__(16) float  g_heads[524288];

// ---------------- helpers ----------------
__device__ __forceinline__ uint32_t smem_u32(const void* p) {
    uint32_t a;
    asm("{ .reg .u64 t; cvta.to.shared.u64 t, %1; cvt.u32.u64 %0, t; }" : "=r"(a) : "l"(p));
    return a;
}
__device__ __forceinline__ uint32_t swz128(uint32_t x) { return x ^ ((x >> 3) & 0x70); }

__device__ __forceinline__ void cp16(uint32_t dst, const void* src) {
    asm volatile("cp.async.cg.shared.global [%0], [%1], 16;"
                 :: "r"(dst), "l"(__cvta_generic_to_global(src)) : "memory");
}
#define CP_COMMIT() asm volatile("cp.async.commit_group;" ::: "memory")
#define CP_WAIT1()  asm volatile("cp.async.wait_group 1;" ::: "memory")

__device__ __forceinline__ void ldsm4(uint32_t* r, uint32_t a) {
    asm volatile("ldmatrix.sync.aligned.m8n8.x4.shared.b16 {%0,%1,%2,%3}, [%4];"
                 : "=r"(r[0]), "=r"(r[1]), "=r"(r[2]), "=r"(r[3]) : "r"(a));
}
__device__ __forceinline__ void mma_f16(float* d, const uint32_t* a, uint32_t b0, uint32_t b1) {
    asm volatile(
        "mma.sync.aligned.m16n8k16.row.col.f32.f16.f16.f32 "
        "{%0,%1,%2,%3}, {%4,%5,%6,%7}, {%8,%9}, {%0,%1,%2,%3};"
        : "+f"(d[0]), "+f"(d[1]), "+f"(d[2]), "+f"(d[3])
        : "r"(a[0]), "r"(a[1]), "r"(a[2]), "r"(a[3]), "r"(b0), "r"(b1));
}

// stage: A 16K | Bh 32K | Bl 32K = 80KB, double buffered = 160KB
static constexpr int STG = 81920;
static constexpr int SMEM_BYTES = 2 * STG;

// ============ GEMM: C[128x256] = fp16 A @ (Bh+Bl)^T, 2 passes ============
// MODE 0: bias+relu -> fp16 store to g_act16 ; MODE 1: fp32 store to g_act2
template <int MODE>
__global__ void __launch_bounds__(256, 1) gemm_kernel(
    const __half* __restrict__ A, const __half* __restrict__ Bh,
    const __half* __restrict__ Bl,
    const float* __restrict__ biasA, const float* __restrict__ biasB,
    int K, int ldA, int a_split)
{
    extern __shared__ char smem[];
    const uint32_t sbase = smem_u32(smem);
    const int tid = threadIdx.x, wid = tid >> 5, lid = tid & 31;
    const int n_base = blockIdx.x * 256;
    const int m_base = blockIdx.y * 128;
    const int a_off = (a_split && n_base >= 1024) ? 1024 : 0;
    const float* bias = (n_base >= 1024) ? biasB : biasA;
    const int NS = K >> 6;

    // warp tile 64x64: 2 warps along M, 4 along N
    const int m0 = (wid & 1) * 64, n0 = (wid >> 1) * 64;
    const int lrow = lid & 15, lcol = (lid >> 4) * 16;
    const int ld_r0 = tid >> 3, ld_c = tid & 7;

    float acc[4][8][4];
#pragma unroll
    for (int mt = 0; mt < 4; ++mt)
#pragma unroll
        for (int j = 0; j < 8; ++j)
#pragma unroll
            for (int q = 0; q < 4; ++q) acc[mt][j][q] = 0.f;

    auto load_stage = [&](int s) {
        if (s < NS) {
            const size_t kb = (size_t)s * 64;
            const uint32_t so = sbase + (uint32_t)(s & 1) * STG;
#pragma unroll
            for (int i = 0; i < 4; ++i) {          // A: 128 rows x 128B
                const int row = ld_r0 + i * 32;
                const uint32_t sw = swz128((uint32_t)(row * 128 + ld_c * 16));
                cp16(so + sw, A + (size_t)(m_base + row) * ldA + a_off + kb + ld_c * 8);
            }
#pragma unroll
            for (int i = 0; i < 8; ++i) {          // B: 256 rows, hi+lo
                const int row = ld_r0 + i * 32;
                const uint32_t sw = swz128((uint32_t)(row * 128 + ld_c * 16));
                const size_t gb = (size_t)(n_base + row) * K + kb + ld_c * 8;
                cp16(so + 16384 + sw, Bh + gb);
                cp16(so + 49152 + sw, Bl + gb);
            }
        }
        CP_COMMIT();
    };

    load_stage(0);

#pragma unroll 1
    for (int s = 0; s < NS; ++s) {
        load_stage(s + 1);
        CP_WAIT1();
        __syncthreads();
        const uint32_t so = sbase + (uint32_t)(s & 1) * STG;
#pragma unroll
        for (int kk = 0; kk < 4; ++kk) {
            const int kb2 = kk * 32;
            uint32_t af[4][4];
#pragma unroll
            for (int mt = 0; mt < 4; ++mt)
                ldsm4(af[mt], so + swz128((uint32_t)((m0 + mt * 16 + lrow) * 128 + kb2 + lcol)));
#pragma unroll
            for (int j2 = 0; j2 < 4; ++j2) {
                uint32_t bh[4], bl[4];
                const uint32_t off = swz128((uint32_t)((n0 + j2 * 16 + lrow) * 128 + kb2 + lcol));
                ldsm4(bh, so + 16384 + off);
                ldsm4(bl, so + 49152 + off);
#pragma unroll
                for (int mt = 0; mt < 4; ++mt)
#pragma unroll
                    for (int h = 0; h < 2; ++h) {
                        float* d = acc[mt][j2 * 2 + h];
                        mma_f16(d, af[mt], bh[h], bh[2 + h]);
                        mma_f16(d, af[mt], bl[h], bl[2 + h]);
                    }
            }
        }
        __syncthreads();
    }

    // epilogue
    const int grp = lid >> 2, qd = lid & 3;
#pragma unroll
    for (int mt = 0; mt < 4; ++mt)
#pragma unroll
        for (int j = 0; j < 8; ++j)
#pragma unroll
            for (int h = 0; h < 2; ++h) {
                const int row = m_base + m0 + mt * 16 + grp + h * 8;
                const int colg = n_base + n0 + (j >> 1) * 16 + (j & 1) * 8 + qd * 2;
                const int cb = colg & 1023;
                float v0 = fmaxf(acc[mt][j][2 * h]     + __ldg(bias + cb), 0.f);
                float v1 = fmaxf(acc[mt][j][2 * h + 1] + __ldg(bias + cb + 1), 0.f);
                if (MODE == 0) {
                    __half2 p = __floats2half2_rn(v0, v1);
                    *reinterpret_cast<uint32_t*>(g_act16 + (size_t)row * 2048 + colg) =
                        *reinterpret_cast<uint32_t*>(&p);
                } else {
                    float2 f; f.x = v0; f.y = v1;
                    *reinterpret_cast<float2*>(g_act2 + (size_t)row * 2048 + colg) = f;
                }
            }
}

// ============ fp32 -> fp16 conversions ============
__global__ void __launch_bounds__(256) conv_half(
    const float* __restrict__ s, __half* __restrict__ d, size_t n4)
{
    const size_t i = (size_t)blockIdx.x * 256 + threadIdx.x;
    if (i >= n4) return;
    float4 v = reinterpret_cast<const float4*>(s)[i];
    __half2 p0 = __floats2half2_rn(v.x, v.y);
    __half2 p1 = __floats2half2_rn(v.z, v.w);
    uint2 o; o.x = *reinterpret_cast<uint32_t*>(&p0); o.y = *reinterpret_cast<uint32_t*>(&p1);
    reinterpret_cast<uint2*>(d)[i] = o;
}
__global__ void __launch_bounds__(256) conv_half_split(
    const float* __restrict__ s, __half* __restrict__ hi,
    __half* __restrict__ lo, size_t n4)
{
    const size_t i = (size_t)blockIdx.x * 256 + threadIdx.x;
    if (i >= n4) return;
    float4 v = reinterpret_cast<const float4*>(s)[i];
    __half h0 = __float2half_rn(v.x), h1 = __float2half_rn(v.y);
    __half h2 = __float2half_rn(v.z), h3 = __float2half_rn(v.w);
    __half2 hp0; hp0.x = h0; hp0.y = h1;
    __half2 hp1; hp1.x = h2; hp1.y = h3;
    uint2 oh; oh.x = *reinterpret_cast<uint32_t*>(&hp0); oh.y = *reinterpret_cast<uint32_t*>(&hp1);
    reinterpret_cast<uint2*>(hi)[i] = oh;
    __half2 lp0; lp0.x = __float2half_rn(v.x - __half2float(h0));
    lp0.y = __float2half_rn(v.y - __half2float(h1));
    __half2 lp1; lp1.x = __float2half_rn(v.z - __half2float(h2));
    lp1.y = __float2half_rn(v.w - __half2float(h3));
    uint2 ol; ol.x = *reinterpret_cast<uint32_t*>(&lp0); ol.y = *reinterpret_cast<uint32_t*>(&lp1);
    reinterpret_cast<uint2*>(lo)[i] = ol;
}

// ============ Heads: 53 dot-products of length 1024 per row ============
__global__ void __launch_bounds__(512) heads_kernel(
    const float* __restrict__ w_cls, const float* __restrict__ b_cls,
    const float* __restrict__ w_delta, const float* __restrict__ b_delta,
    const float* __restrict__ w_pos, const float* __restrict__ b_pos,
    const float* __restrict__ w_emb, const float* __restrict__ b_emb)
{
    const int wid = threadIdx.x >> 5, lid = threadIdx.x & 31;
    const int row = blockIdx.x * 16 + wid;
#pragma unroll 1
    for (int o = 0; o < 53; ++o) {
        const float* Wp; const float* bp; int wr, ac;
        if (o < 3)       { Wp = w_cls;   bp = b_cls;   wr = o;      ac = 0; }
        else if (o < 15) { Wp = w_delta; bp = b_delta; wr = o - 3;  ac = 0; }
        else if (o < 21) { Wp = w_pos;   bp = b_pos;   wr = o - 15; ac = 0; }
        else             { Wp = w_emb;   bp = b_emb;   wr = o - 21; ac = 1024; }
        const float* a = g_act2 + (size_t)row * 2048 + ac;
        const float* w = Wp + (size_t)wr * 1024;
        float s = 0.f;
#pragma unroll 8
        for (int k = lid; k < 1024; k += 32) s += a[k] * w[k];
#pragma unroll
        for (int d = 16; d; d >>= 1) s += __shfl_xor_sync(0xFFFFFFFFu, s, d);
        if (lid == 0) g_heads[(size_t)row * 64 + o] = s + bp[wr];
    }
}

// ============ Postprocess ============
__global__ void __launch_bounds__(128) post_kernel(
    const float* __restrict__ rois, float* __restrict__ out, int out_size)
{
    const int n = blockIdx.x * blockDim.x + threadIdx.x;
    if (n >= 8192) return;
    const float* h = g_heads + (size_t)n * 64;
    float c0 = h[0], c1 = h[1], c2 = h[2];
    float m = fmaxf(c0, fmaxf(c1, c2));
    float e0 = expf(c0 - m), e1 = expf(c1 - m), e2 = expf(c2 - m);
    float inv = 1.f / (e0 + e1 + e2);
    float sc0 = e1 * inv, sc1 = e2 * inv;
    float x1 = rois[n * 5 + 1], y1 = rois[n * 5 + 2];
    float x2 = rois[n * 5 + 3], y2 = rois[n * 5 + 4];
    float bw = x2 - x1, bh = y2 - y1;
    float cx = x1 + 0.5f * bw, cy = y1 + 0.5f * bh;
#pragma unroll
    for (int j = 0; j < 2; ++j) {
        float d0 = h[7 + 4 * j] * 0.1f, d1 = h[8 + 4 * j] * 0.1f;
        float d2 = h[9 + 4 * j] * 0.2f, d3 = h[10 + 4 * j] * 0.2f;
        float p0 = h[17 + 2 * j] * 0.1f, p1 = h[18 + 2 * j] * 0.1f;
        float pcx = d0 * bw + cx, pcy = d1 * bh + cy;
        float pw = expf(d2) * bw, phh = expf(d3) * bh;
        float px = p0 * bw + cx, py = p1 * bh + cy;
        float* ob = out + (size_t)(2 * n + j) * 8;
        ob[0] = pcx - 0.5f * pw;  ob[1] = pcy - 0.5f * phh;
        ob[2] = pcx + 0.5f * pw;  ob[3] = pcy + 0.5f * phh;
        ob[4] = px; ob[5] = py;
        ob[6] = j ? sc1 : sc0;
        ob[7] = (float)(j + 1);
        float* oe = out + 131072 + (size_t)(2 * n + j) * 32;
#pragma unroll
        for (int t = 0; t < 32; ++t) oe[t] = h[21 + t];
    }
    if (n == 0 && out_size > 655360) out[655360] = 2.0f;
}

// ============ launch ============
extern "C" void kernel_launch(void* const* d_in, const int* in_sizes, int n_in,
                              void* d_out, int out_size) {
    const float* pool   = (const float*)d_in[0];
    const float* rois   = (const float*)d_in[1];
    const float* w_fc1  = (const float*)d_in[2];
    const float* b_fc1  = (const float*)d_in[3];
    const float* w_fc2  = (const float*)d_in[4];
    const float* b_fc2  = (const float*)d_in[5];
    const float* w_fc3  = (const float*)d_in[6];
    const float* b_fc3  = (const float*)d_in[7];
    const float* w_fc4  = (const float*)d_in[8];
    const float* b_fc4  = (const float*)d_in[9];
    const float* w_cls  = (const float*)d_in[10];
    const float* b_cls  = (const float*)d_in[11];
    const float* w_delta= (const float*)d_in[12];
    const float* b_delta= (const float*)d_in[13];
    const float* w_pos  = (const float*)d_in[14];
    const float* b_pos  = (const float*)d_in[15];
    const float* w_emb  = (const float*)d_in[16];
    const float* b_emb  = (const float*)d_in[17];
    float* out = (float*)d_out;

    __half *A16, *W13h, *W13l, *W24h, *W24l;
    cudaGetSymbolAddress((void**)&A16,  g_A16);
    cudaGetSymbolAddress((void**)&W13h, g_W13h);
    cudaGetSymbolAddress((void**)&W13l, g_W13l);
    cudaGetSymbolAddress((void**)&W24h, g_w24h);
    cudaGetSymbolAddress((void**)&W24l, g_w24l);
    __half* ACT16;
    cudaGetSymbolAddress((void**)&ACT16, g_act16);

    cudaFuncSetAttribute(gemm_kernel<0>, cudaFuncAttributeMaxDynamicSharedMemorySize, SMEM_BYTES);
    cudaFuncSetAttribute(gemm_kernel<1>, cudaFuncAttributeMaxDynamicSharedMemorySize, SMEM_BYTES);

    // 5 prep launches, gemm1 = launch #6 (ncu -s 5 -c 1 target)
    conv_half<<<100352, 256>>>(pool, A16, 25690112);                          // L1
    conv_half_split<<<12544, 256>>>(w_fc1, W13h,            W13l,            3211264); // L2
    conv_half_split<<<12544, 256>>>(w_fc3, W13h + 12845056, W13l + 12845056, 3211264); // L3
    conv_half_split<<<1024,  256>>>(w_fc2, W24h,            W24l,            262144);  // L4
    conv_half_split<<<1024,  256>>>(w_fc4, W24h + 1048576,  W24l + 1048576,  262144);  // L5

    gemm_kernel<0><<<dim3(8, 64), 256, SMEM_BYTES>>>(A16, W13h, W13l,
                                                     b_fc1, b_fc3, 12544, 12544, 0);   // L6
    gemm_kernel<1><<<dim3(8, 64), 256, SMEM_BYTES>>>(ACT16, W24h, W24l,
                                                     b_fc2, b_fc4, 1024, 2048, 1);
    heads_kernel<<<512, 512>>>(w_cls, b_cls, w_delta, b_delta, w_pos, b_pos, w_emb, b_emb);
    post_kernel<<<64, 128>>>(rois, out, out_size);
}

// round 14
// speedup vs baseline: 5.5373x; 1.5073x over previous
#include <cuda_runtime.h>
#include <cuda_fp16.h>
#include <cstdint>
#include <math.h>

// ---------------- static scratch ----------------
__device__ __align__(16) __half g_A16[102760448];    // 8192x12544 fp16
__device__ __align__(16) __half g_W13[25690112];     // [w1;w3] 2048x12544 fp16
__device__ __align__(16) __half g_w24[2097152];      // [w2;w4] 2048x1024 fp16
__device__ __align__(16) __half g_act16[16777216];   // 8192x2048 fp16
__device__ __align__(16) float  g_act2[16777216];
__device__ __align__(16) float  g_heads[524288];

// ---------------- helpers ----------------
__device__ __forceinline__ uint32_t smem_u32(const void* p) {
    uint32_t a;
    asm("{ .reg .u64 t; cvta.to.shared.u64 t, %1; cvt.u32.u64 %0, t; }" : "=r"(a) : "l"(p));
    return a;
}
__device__ __forceinline__ uint32_t swz128(uint32_t x) { return x ^ ((x >> 3) & 0x70); }

__device__ __forceinline__ void cp16(uint32_t dst, const void* src) {
    asm volatile("cp.async.cg.shared.global [%0], [%1], 16;"
                 :: "r"(dst), "l"(__cvta_generic_to_global(src)) : "memory");
}
#define CP_COMMIT() asm volatile("cp.async.commit_group;" ::: "memory")
#define CP_WAIT2()  asm volatile("cp.async.wait_group 2;" ::: "memory")

__device__ __forceinline__ void ldsm4(uint32_t* r, uint32_t a) {
    asm volatile("ldmatrix.sync.aligned.m8n8.x4.shared.b16 {%0,%1,%2,%3}, [%4];"
                 : "=r"(r[0]), "=r"(r[1]), "=r"(r[2]), "=r"(r[3]) : "r"(a));
}
__device__ __forceinline__ void mma_f16(float* d, const uint32_t* a, uint32_t b0, uint32_t b1) {
    asm volatile(
        "mma.sync.aligned.m16n8k16.row.col.f32.f16.f16.f32 "
        "{%0,%1,%2,%3}, {%4,%5,%6,%7}, {%8,%9}, {%0,%1,%2,%3};"
        : "+f"(d[0]), "+f"(d[1]), "+f"(d[2]), "+f"(d[3])
        : "r"(a[0]), "r"(a[1]), "r"(a[2]), "r"(a[3]), "r"(b0), "r"(b1));
}

// stage: A 16K | B 32K = 48KB, 3 stages = 144KB
static constexpr int STG = 49152;
static constexpr int SMEM_BYTES = 3 * STG;

// ============ GEMM: C[128x256] = fp16 A @ B^T, 1 pass ============
// MODE 0: bias+relu -> fp16 store to g_act16 ; MODE 1: fp32 store to g_act2
template <int MODE>
__global__ void __launch_bounds__(256, 1) gemm_kernel(
    const __half* __restrict__ A, const __half* __restrict__ B,
    const float* __restrict__ biasA, const float* __restrict__ biasB,
    int K, int ldA, int a_split)
{
    extern __shared__ char smem[];
    const uint32_t sbase = smem_u32(smem);
    const int tid = threadIdx.x, wid = tid >> 5, lid = tid & 31;
    const int n_base = blockIdx.x * 256;
    const int m_base = blockIdx.y * 128;
    const int a_off = (a_split && n_base >= 1024) ? 1024 : 0;
    const float* bias = (n_base >= 1024) ? biasB : biasA;
    const int NS = K >> 6;

    // warp tile 64x64: 2 warps along M, 4 along N
    const int m0 = (wid & 1) * 64, n0 = (wid >> 1) * 64;
    const int lrow = lid & 15, lcol = (lid >> 4) * 16;
    const int ld_r0 = tid >> 3, ld_c = tid & 7;

    float acc[4][8][4];
#pragma unroll
    for (int mt = 0; mt < 4; ++mt)
#pragma unroll
        for (int j = 0; j < 8; ++j)
#pragma unroll
            for (int q = 0; q < 4; ++q) acc[mt][j][q] = 0.f;

    auto load_stage = [&](int s) {
        if (s < NS) {
            const size_t kb = (size_t)s * 64;
            const uint32_t so = sbase + (uint32_t)(s % 3) * STG;
#pragma unroll
            for (int i = 0; i < 4; ++i) {          // A: 128 rows x 128B
                const int row = ld_r0 + i * 32;
                const uint32_t sw = swz128((uint32_t)(row * 128 + ld_c * 16));
                cp16(so + sw, A + (size_t)(m_base + row) * ldA + a_off + kb + ld_c * 8);
            }
#pragma unroll
            for (int i = 0; i < 8; ++i) {          // B: 256 rows x 128B
                const int row = ld_r0 + i * 32;
                const uint32_t sw = swz128((uint32_t)(row * 128 + ld_c * 16));
                cp16(so + 16384 + sw, B + (size_t)(n_base + row) * K + kb + ld_c * 8);
            }
        }
        CP_COMMIT();
    };

    load_stage(0);
    load_stage(1);

#pragma unroll 1
    for (int s = 0; s < NS; ++s) {
        load_stage(s + 2);
        CP_WAIT2();
        __syncthreads();
        const uint32_t so = sbase + (uint32_t)(s % 3) * STG;
#pragma unroll
        for (int kk = 0; kk < 4; ++kk) {
            const int kb2 = kk * 32;
            uint32_t af[4][4];
#pragma unroll
            for (int mt = 0; mt < 4; ++mt)
                ldsm4(af[mt], so + swz128((uint32_t)((m0 + mt * 16 + lrow) * 128 + kb2 + lcol)));
#pragma unroll
            for (int j2 = 0; j2 < 4; ++j2) {
                uint32_t bf[4];
                ldsm4(bf, so + 16384 +
                      swz128((uint32_t)((n0 + j2 * 16 + lrow) * 128 + kb2 + lcol)));
#pragma unroll
                for (int mt = 0; mt < 4; ++mt)
#pragma unroll
                    for (int h = 0; h < 2; ++h)
                        mma_f16(acc[mt][j2 * 2 + h], af[mt], bf[h], bf[2 + h]);
            }
        }
        __syncthreads();
    }

    // epilogue
    const int grp = lid >> 2, qd = lid & 3;
#pragma unroll
    for (int mt = 0; mt < 4; ++mt)
#pragma unroll
        for (int j = 0; j < 8; ++j)
#pragma unroll
            for (int h = 0; h < 2; ++h) {
                const int row = m_base + m0 + mt * 16 + grp + h * 8;
                const int colg = n_base + n0 + (j >> 1) * 16 + (j & 1) * 8 + qd * 2;
                const int cb = colg & 1023;
                float v0 = fmaxf(acc[mt][j][2 * h]     + __ldg(bias + cb), 0.f);
                float v1 = fmaxf(acc[mt][j][2 * h + 1] + __ldg(bias + cb + 1), 0.f);
                if (MODE == 0) {
                    __half2 p = __floats2half2_rn(v0, v1);
                    *reinterpret_cast<uint32_t*>(g_act16 + (size_t)row * 2048 + colg) =
                        *reinterpret_cast<uint32_t*>(&p);
                } else {
                    float2 f; f.x = v0; f.y = v1;
                    *reinterpret_cast<float2*>(g_act2 + (size_t)row * 2048 + colg) = f;
                }
            }
}

// ============ fp32 -> fp16 conversion ============
__global__ void __launch_bounds__(256) conv_half(
    const float* __restrict__ s, __half* __restrict__ d, size_t n4)
{
    const size_t i = (size_t)blockIdx.x * 256 + threadIdx.x;
    if (i >= n4) return;
    float4 v = reinterpret_cast<const float4*>(s)[i];
    __half2 p0 = __floats2half2_rn(v.x, v.y);
    __half2 p1 = __floats2half2_rn(v.z, v.w);
    uint2 o; o.x = *reinterpret_cast<uint32_t*>(&p0); o.y = *reinterpret_cast<uint32_t*>(&p1);
    reinterpret_cast<uint2*>(d)[i] = o;
}

// ============ Heads: 53 dot-products of length 1024 per row ============
__global__ void __launch_bounds__(512) heads_kernel(
    const float* __restrict__ w_cls, const float* __restrict__ b_cls,
    const float* __restrict__ w_delta, const float* __restrict__ b_delta,
    const float* __restrict__ w_pos, const float* __restrict__ b_pos,
    const float* __restrict__ w_emb, const float* __restrict__ b_emb)
{
    const int wid = threadIdx.x >> 5, lid = threadIdx.x & 31;
    const int row = blockIdx.x * 16 + wid;
#pragma unroll 1
    for (int o = 0; o < 53; ++o) {
        const float* Wp; const float* bp; int wr, ac;
        if (o < 3)       { Wp = w_cls;   bp = b_cls;   wr = o;      ac = 0; }
        else if (o < 15) { Wp = w_delta; bp = b_delta; wr = o - 3;  ac = 0; }
        else if (o < 21) { Wp = w_pos;   bp = b_pos;   wr = o - 15; ac = 0; }
        else             { Wp = w_emb;   bp = b_emb;   wr = o - 21; ac = 1024; }
        const float* a = g_act2 + (size_t)row * 2048 + ac;
        const float* w = Wp + (size_t)wr * 1024;
        float s = 0.f;
#pragma unroll 8
        for (int k = lid; k < 1024; k += 32) s += a[k] * w[k];
#pragma unroll
        for (int d = 16; d; d >>= 1) s += __shfl_xor_sync(0xFFFFFFFFu, s, d);
        if (lid == 0) g_heads[(size_t)row * 64 + o] = s + bp[wr];
    }
}

// ============ Postprocess ============
__global__ void __launch_bounds__(128) post_kernel(
    const float* __restrict__ rois, float* __restrict__ out, int out_size)
{
    const int n = blockIdx.x * blockDim.x + threadIdx.x;
    if (n >= 8192) return;
    const float* h = g_heads + (size_t)n * 64;
    float c0 = h[0], c1 = h[1], c2 = h[2];
    float m = fmaxf(c0, fmaxf(c1, c2));
    float e0 = expf(c0 - m), e1 = expf(c1 - m), e2 = expf(c2 - m);
    float inv = 1.f / (e0 + e1 + e2);
    float sc0 = e1 * inv, sc1 = e2 * inv;
    float x1 = rois[n * 5 + 1], y1 = rois[n * 5 + 2];
    float x2 = rois[n * 5 + 3], y2 = rois[n * 5 + 4];
    float bw = x2 - x1, bh = y2 - y1;
    float cx = x1 + 0.5f * bw, cy = y1 + 0.5f * bh;
#pragma unroll
    for (int j = 0; j < 2; ++j) {
        float d0 = h[7 + 4 * j] * 0.1f, d1 = h[8 + 4 * j] * 0.1f;
        float d2 = h[9 + 4 * j] * 0.2f, d3 = h[10 + 4 * j] * 0.2f;
        float p0 = h[17 + 2 * j] * 0.1f, p1 = h[18 + 2 * j] * 0.1f;
        float pcx = d0 * bw + cx, pcy = d1 * bh + cy;
        float pw = expf(d2) * bw, phh = expf(d3) * bh;
        float px = p0 * bw + cx, py = p1 * bh + cy;
        float* ob = out + (size_t)(2 * n + j) * 8;
        ob[0] = pcx - 0.5f * pw;  ob[1] = pcy - 0.5f * phh;
        ob[2] = pcx + 0.5f * pw;  ob[3] = pcy + 0.5f * phh;
        ob[4] = px; ob[5] = py;
        ob[6] = j ? sc1 : sc0;
        ob[7] = (float)(j + 1);
        float* oe = out + 131072 + (size_t)(2 * n + j) * 32;
#pragma unroll
        for (int t = 0; t < 32; ++t) oe[t] = h[21 + t];
    }
    if (n == 0 && out_size > 655360) out[655360] = 2.0f;
}

// ============ launch ============
extern "C" void kernel_launch(void* const* d_in, const int* in_sizes, int n_in,
                              void* d_out, int out_size) {
    const float* pool   = (const float*)d_in[0];
    const float* rois   = (const float*)d_in[1];
    const float* w_fc1  = (const float*)d_in[2];
    const float* b_fc1  = (const float*)d_in[3];
    const float* w_fc2  = (const float*)d_in[4];
    const float* b_fc2  = (const float*)d_in[5];
    const float* w_fc3  = (const float*)d_in[6];
    const float* b_fc3  = (const float*)d_in[7];
    const float* w_fc4  = (const float*)d_in[8];
    const float* b_fc4  = (const float*)d_in[9];
    const float* w_cls  = (const float*)d_in[10];
    const float* b_cls  = (const float*)d_in[11];
    const float* w_delta= (const float*)d_in[12];
    const float* b_delta= (const float*)d_in[13];
    const float* w_pos  = (const float*)d_in[14];
    const float* b_pos  = (const float*)d_in[15];
    const float* w_emb  = (const float*)d_in[16];
    const float* b_emb  = (const float*)d_in[17];
    float* out = (float*)d_out;

    __half *A16, *W13, *W24, *ACT16;
    cudaGetSymbolAddress((void**)&A16,  g_A16);
    cudaGetSymbolAddress((void**)&W13,  g_W13);
    cudaGetSymbolAddress((void**)&W24,  g_w24);
    cudaGetSymbolAddress((void**)&ACT16, g_act16);

    cudaFuncSetAttribute(gemm_kernel<0>, cudaFuncAttributeMaxDynamicSharedMemorySize, SMEM_BYTES);
    cudaFuncSetAttribute(gemm_kernel<1>, cudaFuncAttributeMaxDynamicSharedMemorySize, SMEM_BYTES);

    // 5 prep launches, gemm1 = launch #6 (ncu -s 5 -c 1 target)
    conv_half<<<100352, 256>>>(pool,  A16,             25690112);   // L1
    conv_half<<<12544,  256>>>(w_fc1, W13,             3211264);    // L2
    conv_half<<<12544,  256>>>(w_fc3, W13 + 12845056,  3211264);    // L3
    conv_half<<<1024,   256>>>(w_fc2, W24,             262144);     // L4
    conv_half<<<1024,   256>>>(w_fc4, W24 + 1048576,   262144);     // L5

    gemm_kernel<0><<<dim3(8, 64), 256, SMEM_BYTES>>>(A16, W13,
                                                     b_fc1, b_fc3, 12544, 12544, 0);   // L6
    gemm_kernel<1><<<dim3(8, 64), 256, SMEM_BYTES>>>(ACT16, W24,
                                                     b_fc2, b_fc4, 1024, 2048, 1);
    heads_kernel<<<512, 512>>>(w_cls, b_cls, w_delta, b_delta, w_pos, b_pos, w_emb, b_emb);
    post_kernel<<<64, 128>>>(rois, out, out_size);
}

// round 15
// speedup vs baseline: 6.3463x; 1.1461x over previous
#include <cuda_runtime.h>
#include <cuda_fp16.h>
#include <cstdint>
#include <math.h>

// ---------------- static scratch ----------------
__device__ __align__(16) __half g_A16[102760448];    // 8192x12544 fp16
__device__ __align__(16) __half g_W13[25690112];     // [w1;w3] 2048x12544 fp16
__device__ __align__(16) __half g_w24[2097152];      // [w2;w4] 2048x1024 fp16
__device__ __align__(16) __half g_act16[16777216];   // 8192x2048 fp16
__device__ __align__(16) float  g_act2[16777216];
__device__ __align__(16) float  g_heads[524288];

// ---------------- helpers ----------------
__device__ __forceinline__ uint32_t smem_u32(const void* p) {
    uint32_t a;
    asm("{ .reg .u64 t; cvta.to.shared.u64 t, %1; cvt.u32.u64 %0, t; }" : "=r"(a) : "l"(p));
    return a;
}
__device__ __forceinline__ uint32_t swz128(uint32_t x) { return x ^ ((x >> 3) & 0x70); }

__device__ __forceinline__ void cp16(uint32_t dst, const void* src) {
    asm volatile("cp.async.cg.shared.global [%0], [%1], 16;"
                 :: "r"(dst), "l"(__cvta_generic_to_global(src)) : "memory");
}
#define CP_COMMIT() asm volatile("cp.async.commit_group;" ::: "memory")
#define CP_WAIT2()  asm volatile("cp.async.wait_group 2;" ::: "memory")

__device__ __forceinline__ void ldsm4(uint32_t* r, uint32_t a) {
    asm volatile("ldmatrix.sync.aligned.m8n8.x4.shared.b16 {%0,%1,%2,%3}, [%4];"
                 : "=r"(r[0]), "=r"(r[1]), "=r"(r[2]), "=r"(r[3]) : "r"(a));
}
__device__ __forceinline__ void mma_f16(float* d, const uint32_t* a, uint32_t b0, uint32_t b1) {
    asm volatile(
        "mma.sync.aligned.m16n8k16.row.col.f32.f16.f16.f32 "
        "{%0,%1,%2,%3}, {%4,%5,%6,%7}, {%8,%9}, {%0,%1,%2,%3};"
        : "+f"(d[0]), "+f"(d[1]), "+f"(d[2]), "+f"(d[3])
        : "r"(a[0]), "r"(a[1]), "r"(a[2]), "r"(a[3]), "r"(b0), "r"(b1));
}

// stage: A 16K | B 16K = 32KB, 3 stages = 96KB, 2 CTAs/SM
static constexpr int STG = 32768;
static constexpr int SMEM_BYTES = 3 * STG;

// ============ GEMM: C[128x128] = fp16 A @ B^T, 1 pass, occ 2 ============
// 128 threads, 4 warps as 2x2 of 64x64 tiles.
// MODE 0: bias+relu -> fp16 store to g_act16 ; MODE 1: fp32 store to g_act2
template <int MODE>
__global__ void __launch_bounds__(128, 2) gemm_kernel(
    const __half* __restrict__ A, const __half* __restrict__ B,
    const float* __restrict__ biasA, const float* __restrict__ biasB,
    int K, int ldA, int a_split)
{
    extern __shared__ char smem[];
    const uint32_t sbase = smem_u32(smem);
    const int tid = threadIdx.x, wid = tid >> 5, lid = tid & 31;
    const int n_base = blockIdx.x * 128;
    const int m_base = blockIdx.y * 128;
    const int a_off = (a_split && n_base >= 1024) ? 1024 : 0;
    const float* bias = (n_base >= 1024) ? biasB : biasA;
    const int NS = K >> 6;

    // warp tile 64x64: 2 warps along M, 2 along N
    const int m0 = (wid & 1) * 64, n0 = (wid >> 1) * 64;
    const int lrow = lid & 15, lcol = (lid >> 4) * 16;
    const int ld_r0 = tid >> 3, ld_c = tid & 7;   // 16 rows/pass, 8 passes

    float acc[4][8][4];
#pragma unroll
    for (int mt = 0; mt < 4; ++mt)
#pragma unroll
        for (int j = 0; j < 8; ++j)
#pragma unroll
            for (int q = 0; q < 4; ++q) acc[mt][j][q] = 0.f;

    auto load_stage = [&](int s) {
        if (s < NS) {
            const size_t kb = (size_t)s * 64;
            const uint32_t so = sbase + (uint32_t)(s % 3) * STG;
#pragma unroll
            for (int i = 0; i < 8; ++i) {
                const int row = ld_r0 + i * 16;
                const uint32_t sw = swz128((uint32_t)(row * 128 + ld_c * 16));
                cp16(so + sw,
                     A + (size_t)(m_base + row) * ldA + a_off + kb + ld_c * 8);
                cp16(so + 16384 + sw,
                     B + (size_t)(n_base + row) * K + kb + ld_c * 8);
            }
        }
        CP_COMMIT();
    };

    load_stage(0);
    load_stage(1);

#pragma unroll 1
    for (int s = 0; s < NS; ++s) {
        load_stage(s + 2);
        CP_WAIT2();
        __syncthreads();
        const uint32_t so = sbase + (uint32_t)(s % 3) * STG;
#pragma unroll
        for (int kk = 0; kk < 4; ++kk) {
            const int kb2 = kk * 32;
            uint32_t af[4][4];
#pragma unroll
            for (int mt = 0; mt < 4; ++mt)
                ldsm4(af[mt], so + swz128((uint32_t)((m0 + mt * 16 + lrow) * 128 + kb2 + lcol)));
#pragma unroll
            for (int j2 = 0; j2 < 4; ++j2) {
                uint32_t bf[4];
                ldsm4(bf, so + 16384 +
                      swz128((uint32_t)((n0 + j2 * 16 + lrow) * 128 + kb2 + lcol)));
#pragma unroll
                for (int mt = 0; mt < 4; ++mt)
#pragma unroll
                    for (int h = 0; h < 2; ++h)
                        mma_f16(acc[mt][j2 * 2 + h], af[mt], bf[h], bf[2 + h]);
            }
        }
        __syncthreads();
    }

    // epilogue
    const int grp = lid >> 2, qd = lid & 3;
#pragma unroll
    for (int mt = 0; mt < 4; ++mt)
#pragma unroll
        for (int j = 0; j < 8; ++j)
#pragma unroll
            for (int h = 0; h < 2; ++h) {
                const int row = m_base + m0 + mt * 16 + grp + h * 8;
                const int colg = n_base + n0 + (j >> 1) * 16 + (j & 1) * 8 + qd * 2;
                const int cb = colg & 1023;
                float v0 = fmaxf(acc[mt][j][2 * h]     + __ldg(bias + cb), 0.f);
                float v1 = fmaxf(acc[mt][j][2 * h + 1] + __ldg(bias + cb + 1), 0.f);
                if (MODE == 0) {
                    __half2 p = __floats2half2_rn(v0, v1);
                    *reinterpret_cast<uint32_t*>(g_act16 + (size_t)row * 2048 + colg) =
                        *reinterpret_cast<uint32_t*>(&p);
                } else {
                    float2 f; f.x = v0; f.y = v1;
                    *reinterpret_cast<float2*>(g_act2 + (size_t)row * 2048 + colg) = f;
                }
            }
}

// ============ fused fp32 -> fp16 conversion (all 5 tensors) ============
// float4-index ranges: A [0,25690112) w1 [..,28901376) w3 [..,32112640)
//                      w2 [..,32374784) w4 [..,32636928)
__global__ void __launch_bounds__(256) conv_all(
    const float* __restrict__ pool, const float* __restrict__ w1,
    const float* __restrict__ w3, const float* __restrict__ w2,
    const float* __restrict__ w4)
{
    const size_t i = (size_t)blockIdx.x * 256 + threadIdx.x;
    const float* s; uint2* d; size_t li;
    if (i < 25690112)      { s = pool; d = (uint2*)g_A16;             li = i; }
    else if (i < 28901376) { s = w1;   d = (uint2*)g_W13;             li = i - 25690112; }
    else if (i < 32112640) { s = w3;   d = (uint2*)g_W13 + 3211264;   li = i - 28901376; }
    else if (i < 32374784) { s = w2;   d = (uint2*)g_w24;             li = i - 32112640; }
    else if (i < 32636928) { s = w4;   d = (uint2*)g_w24 + 262144;    li = i - 32374784; }
    else return;
    float4 v = reinterpret_cast<const float4*>(s)[li];
    __half2 p0 = __floats2half2_rn(v.x, v.y);
    __half2 p1 = __floats2half2_rn(v.z, v.w);
    uint2 o; o.x = *reinterpret_cast<uint32_t*>(&p0); o.y = *reinterpret_cast<uint32_t*>(&p1);
    d[li] = o;
}

// ============ Heads: 53 dot-products of length 1024 per row ============
__global__ void __launch_bounds__(512) heads_kernel(
    const float* __restrict__ w_cls, const float* __restrict__ b_cls,
    const float* __restrict__ w_delta, const float* __restrict__ b_delta,
    const float* __restrict__ w_pos, const float* __restrict__ b_pos,
    const float* __restrict__ w_emb, const float* __restrict__ b_emb)
{
    const int wid = threadIdx.x >> 5, lid = threadIdx.x & 31;
    const int row = blockIdx.x * 16 + wid;
#pragma unroll 1
    for (int o = 0; o < 53; ++o) {
        const float* Wp; const float* bp; int wr, ac;
        if (o < 3)       { Wp = w_cls;   bp = b_cls;   wr = o;      ac = 0; }
        else if (o < 15) { Wp = w_delta; bp = b_delta; wr = o - 3;  ac = 0; }
        else if (o < 21) { Wp = w_pos;   bp = b_pos;   wr = o - 15; ac = 0; }
        else             { Wp = w_emb;   bp = b_emb;   wr = o - 21; ac = 1024; }
        const float* a = g_act2 + (size_t)row * 2048 + ac;
        const float* w = Wp + (size_t)wr * 1024;
        float s = 0.f;
#pragma unroll 8
        for (int k = lid; k < 1024; k += 32) s += a[k] * w[k];
#pragma unroll
        for (int d = 16; d; d >>= 1) s += __shfl_xor_sync(0xFFFFFFFFu, s, d);
        if (lid == 0) g_heads[(size_t)row * 64 + o] = s + bp[wr];
    }
}

// ============ Postprocess ============
__global__ void __launch_bounds__(128) post_kernel(
    const float* __restrict__ rois, float* __restrict__ out, int out_size)
{
    const int n = blockIdx.x * blockDim.x + threadIdx.x;
    if (n >= 8192) return;
    const float* h = g_heads + (size_t)n * 64;
    float c0 = h[0], c1 = h[1], c2 = h[2];
    float m = fmaxf(c0, fmaxf(c1, c2));
    float e0 = expf(c0 - m), e1 = expf(c1 - m), e2 = expf(c2 - m);
    float inv = 1.f / (e0 + e1 + e2);
    float sc0 = e1 * inv, sc1 = e2 * inv;
    float x1 = rois[n * 5 + 1], y1 = rois[n * 5 + 2];
    float x2 = rois[n * 5 + 3], y2 = rois[n * 5 + 4];
    float bw = x2 - x1, bh = y2 - y1;
    float cx = x1 + 0.5f * bw, cy = y1 + 0.5f * bh;
#pragma unroll
    for (int j = 0; j < 2; ++j) {
        float d0 = h[7 + 4 * j] * 0.1f, d1 = h[8 + 4 * j] * 0.1f;
        float d2 = h[9 + 4 * j] * 0.2f, d3 = h[10 + 4 * j] * 0.2f;
        float p0 = h[17 + 2 * j] * 0.1f, p1 = h[18 + 2 * j] * 0.1f;
        float pcx = d0 * bw + cx, pcy = d1 * bh + cy;
        float pw = expf(d2) * bw, phh = expf(d3) * bh;
        float px = p0 * bw + cx, py = p1 * bh + cy;
        float* ob = out + (size_t)(2 * n + j) * 8;
        ob[0] = pcx - 0.5f * pw;  ob[1] = pcy - 0.5f * phh;
        ob[2] = pcx + 0.5f * pw;  ob[3] = pcy + 0.5f * phh;
        ob[4] = px; ob[5] = py;
        ob[6] = j ? sc1 : sc0;
        ob[7] = (float)(j + 1);
        float* oe = out + 131072 + (size_t)(2 * n + j) * 32;
#pragma unroll
        for (int t = 0; t < 32; ++t) oe[t] = h[21 + t];
    }
    if (n == 0 && out_size > 655360) out[655360] = 2.0f;
}

// ============ launch ============
extern "C" void kernel_launch(void* const* d_in, const int* in_sizes, int n_in,
                              void* d_out, int out_size) {
    const float* pool   = (const float*)d_in[0];
    const float* rois   = (const float*)d_in[1];
    const float* w_fc1  = (const float*)d_in[2];
    const float* b_fc1  = (const float*)d_in[3];
    const float* w_fc2  = (const float*)d_in[4];
    const float* b_fc2  = (const float*)d_in[5];
    const float* w_fc3  = (const float*)d_in[6];
    const float* b_fc3  = (const float*)d_in[7];
    const float* w_fc4  = (const float*)d_in[8];
    const float* b_fc4  = (const float*)d_in[9];
    const float* w_cls  = (const float*)d_in[10];
    const float* b_cls  = (const float*)d_in[11];
    const float* w_delta= (const float*)d_in[12];
    const float* b_delta= (const float*)d_in[13];
    const float* w_pos  = (const float*)d_in[14];
    const float* b_pos  = (const float*)d_in[15];
    const float* w_emb  = (const float*)d_in[16];
    const float* b_emb  = (const float*)d_in[17];
    float* out = (float*)d_out;

    __half *A16, *W13, *W24, *ACT16;
    cudaGetSymbolAddress((void**)&A16,  g_A16);
    cudaGetSymbolAddress((void**)&W13,  g_W13);
    cudaGetSymbolAddress((void**)&W24,  g_w24);
    cudaGetSymbolAddress((void**)&ACT16, g_act16);

    cudaFuncSetAttribute(gemm_kernel<0>, cudaFuncAttributeMaxDynamicSharedMemorySize, SMEM_BYTES);
    cudaFuncSetAttribute(gemm_kernel<1>, cudaFuncAttributeMaxDynamicSharedMemorySize, SMEM_BYTES);

    conv_all<<<127488, 256>>>(pool, w_fc1, w_fc3, w_fc2, w_fc4);

    gemm_kernel<0><<<dim3(16, 64), 128, SMEM_BYTES>>>(A16, W13,
                                                      b_fc1, b_fc3, 12544, 12544, 0);
    gemm_kernel<1><<<dim3(16, 64), 128, SMEM_BYTES>>>(ACT16, W24,
                                                      b_fc2, b_fc4, 1024, 2048, 1);
    heads_kernel<<<512, 512>>>(w_cls, b_cls, w_delta, b_delta, w_pos, b_pos, w_emb, b_emb);
    post_kernel<<<64, 128>>>(rois, out, out_size);
}

// round 16
// speedup vs baseline: 7.1101x; 1.1204x over previous
#include <cuda_runtime.h>
#include <cuda_fp16.h>
#include <cstdint>
#include <math.h>

// ---------------- static scratch ----------------
__device__ __align__(16) __half g_A16[102760448];    // 8192x12544 fp16; after GEMM1, reused: act2 fp16 [8192x2048]
__device__ __align__(16) __half g_W13[25690112];     // [w1;w3] 2048x12544 fp16
__device__ __align__(16) __half g_w24[2097152];      // [w2;w4] 2048x1024 fp16
__device__ __align__(16) __half g_act16[16777216];   // 8192x2048 fp16 (act1)
__device__ __align__(16) __half g_whead[131072];     // 64x2048 fp16, zero-padded head weights
__device__ float g_hbias[64];
__device__ __align__(16) float  g_heads[524288];     // 8192x64

// ---------------- helpers ----------------
__device__ __forceinline__ uint32_t smem_u32(const void* p) {
    uint32_t a;
    asm("{ .reg .u64 t; cvta.to.shared.u64 t, %1; cvt.u32.u64 %0, t; }" : "=r"(a) : "l"(p));
    return a;
}
__device__ __forceinline__ uint32_t swz128(uint32_t x) { return x ^ ((x >> 3) & 0x70); }

__device__ __forceinline__ void cp16(uint32_t dst, const void* src) {
    asm volatile("cp.async.cg.shared.global [%0], [%1], 16;"
                 :: "r"(dst), "l"(__cvta_generic_to_global(src)) : "memory");
}
#define CP_COMMIT() asm volatile("cp.async.commit_group;" ::: "memory")
#define CP_WAIT2()  asm volatile("cp.async.wait_group 2;" ::: "memory")

__device__ __forceinline__ void ldsm4(uint32_t* r, uint32_t a) {
    asm volatile("ldmatrix.sync.aligned.m8n8.x4.shared.b16 {%0,%1,%2,%3}, [%4];"
                 : "=r"(r[0]), "=r"(r[1]), "=r"(r[2]), "=r"(r[3]) : "r"(a));
}
__device__ __forceinline__ void mma_f16(float* d, const uint32_t* a, uint32_t b0, uint32_t b1) {
    asm volatile(
        "mma.sync.aligned.m16n8k16.row.col.f32.f16.f16.f32 "
        "{%0,%1,%2,%3}, {%4,%5,%6,%7}, {%8,%9}, {%0,%1,%2,%3};"
        : "+f"(d[0]), "+f"(d[1]), "+f"(d[2]), "+f"(d[3])
        : "r"(a[0]), "r"(a[1]), "r"(a[2]), "r"(a[3]), "r"(b0), "r"(b1));
}

// stage: A 16K | B 16K = 32KB, 3 stages = 96KB, 2 CTAs/SM
static constexpr int STG = 32768;
static constexpr int SMEM_BYTES = 3 * STG;

// ============ GEMM: C[128x128] = fp16 A @ B^T, 1 pass, occ 2 ============
// MODE 0: bias+relu -> fp16 to g_act16 ; MODE 1: bias+relu -> fp16 to g_A16 (act2)
template <int MODE>
__global__ void __launch_bounds__(128, 2) gemm_kernel(
    const __half* __restrict__ A, const __half* __restrict__ B,
    const float* __restrict__ biasA, const float* __restrict__ biasB,
    int K, int ldA, int a_split)
{
    extern __shared__ char smem[];
    const uint32_t sbase = smem_u32(smem);
    const int tid = threadIdx.x, wid = tid >> 5, lid = tid & 31;
    const int n_base = blockIdx.x * 128;
    const int m_base = blockIdx.y * 128;
    const int a_off = (a_split && n_base >= 1024) ? 1024 : 0;
    const float* bias = (n_base >= 1024) ? biasB : biasA;
    const int NS = K >> 6;

    const int m0 = (wid & 1) * 64, n0 = (wid >> 1) * 64;
    const int lrow = lid & 15, lcol = (lid >> 4) * 16;
    const int ld_r0 = tid >> 3, ld_c = tid & 7;

    float acc[4][8][4];
#pragma unroll
    for (int mt = 0; mt < 4; ++mt)
#pragma unroll
        for (int j = 0; j < 8; ++j)
#pragma unroll
            for (int q = 0; q < 4; ++q) acc[mt][j][q] = 0.f;

    auto load_stage = [&](int s) {
        if (s < NS) {
            const size_t kb = (size_t)s * 64;
            const uint32_t so = sbase + (uint32_t)(s % 3) * STG;
#pragma unroll
            for (int i = 0; i < 8; ++i) {
                const int row = ld_r0 + i * 16;
                const uint32_t sw = swz128((uint32_t)(row * 128 + ld_c * 16));
                cp16(so + sw,
                     A + (size_t)(m_base + row) * ldA + a_off + kb + ld_c * 8);
                cp16(so + 16384 + sw,
                     B + (size_t)(n_base + row) * K + kb + ld_c * 8);
            }
        }
        CP_COMMIT();
    };

    load_stage(0);
    load_stage(1);

#pragma unroll 1
    for (int s = 0; s < NS; ++s) {
        load_stage(s + 2);
        CP_WAIT2();
        __syncthreads();
        const uint32_t so = sbase + (uint32_t)(s % 3) * STG;
#pragma unroll
        for (int kk = 0; kk < 4; ++kk) {
            const int kb2 = kk * 32;
            uint32_t af[4][4];
#pragma unroll
            for (int mt = 0; mt < 4; ++mt)
                ldsm4(af[mt], so + swz128((uint32_t)((m0 + mt * 16 + lrow) * 128 + kb2 + lcol)));
#pragma unroll
            for (int j2 = 0; j2 < 4; ++j2) {
                uint32_t bf[4];
                ldsm4(bf, so + 16384 +
                      swz128((uint32_t)((n0 + j2 * 16 + lrow) * 128 + kb2 + lcol)));
#pragma unroll
                for (int mt = 0; mt < 4; ++mt)
#pragma unroll
                    for (int h = 0; h < 2; ++h)
                        mma_f16(acc[mt][j2 * 2 + h], af[mt], bf[h], bf[2 + h]);
            }
        }
        __syncthreads();
    }

    const int grp = lid >> 2, qd = lid & 3;
#pragma unroll
    for (int mt = 0; mt < 4; ++mt)
#pragma unroll
        for (int j = 0; j < 8; ++j)
#pragma unroll
            for (int h = 0; h < 2; ++h) {
                const int row = m_base + m0 + mt * 16 + grp + h * 8;
                const int colg = n_base + n0 + (j >> 1) * 16 + (j & 1) * 8 + qd * 2;
                const int cb = colg & 1023;
                float v0 = fmaxf(acc[mt][j][2 * h]     + __ldg(bias + cb), 0.f);
                float v1 = fmaxf(acc[mt][j][2 * h + 1] + __ldg(bias + cb + 1), 0.f);
                __half2 p = __floats2half2_rn(v0, v1);
                __half* dst = (MODE == 0) ? g_act16 : g_A16;
                *reinterpret_cast<uint32_t*>(dst + (size_t)row * 2048 + colg) =
                    *reinterpret_cast<uint32_t*>(&p);
            }
}

// ============ Heads GEMM: [8192,2048] x whead^T[2048,64] -> g_heads fp32 ====
// CTA 64x64, 128 threads (4 warps of 32x32), 3-stage.
static constexpr int HSTG = 16384;   // A 8K | B 8K
static constexpr int HSMEM = 3 * HSTG;

__global__ void __launch_bounds__(128, 2) heads_gemm(const __half* __restrict__ A)
{
    extern __shared__ char smem[];
    const uint32_t sbase = smem_u32(smem);
    const int tid = threadIdx.x, wid = tid >> 5, lid = tid & 31;
    const int m_base = blockIdx.x * 64;
    const int NS = 32;   // K=2048

    const int m0 = (wid & 1) * 32, n0 = (wid >> 1) * 32;
    const int lrow = lid & 15, lcol = (lid >> 4) * 16;
    const int ld_r0 = tid >> 3, ld_c = tid & 7;   // 16 rows/pass, 4 passes over 64 rows

    float acc[2][4][4];
#pragma unroll
    for (int mt = 0; mt < 2; ++mt)
#pragma unroll
        for (int j = 0; j < 4; ++j)
#pragma unroll
            for (int q = 0; q < 4; ++q) acc[mt][j][q] = 0.f;

    auto load_stage = [&](int s) {
        if (s < NS) {
            const size_t kb = (size_t)s * 64;
            const uint32_t so = sbase + (uint32_t)(s % 3) * HSTG;
#pragma unroll
            for (int i = 0; i < 4; ++i) {
                const int row = ld_r0 + i * 16;
                const uint32_t sw = swz128((uint32_t)(row * 128 + ld_c * 16));
                cp16(so + sw, A + (size_t)(m_base + row) * 2048 + kb + ld_c * 8);
                cp16(so + 8192 + sw, g_whead + (size_t)row * 2048 + kb + ld_c * 8);
            }
        }
        CP_COMMIT();
    };

    load_stage(0);
    load_stage(1);

#pragma unroll 1
    for (int s = 0; s < NS; ++s) {
        load_stage(s + 2);
        CP_WAIT2();
        __syncthreads();
        const uint32_t so = sbase + (uint32_t)(s % 3) * HSTG;
#pragma unroll
        for (int kk = 0; kk < 4; ++kk) {
            const int kb2 = kk * 32;
            uint32_t af[2][4];
#pragma unroll
            for (int mt = 0; mt < 2; ++mt)
                ldsm4(af[mt], so + swz128((uint32_t)((m0 + mt * 16 + lrow) * 128 + kb2 + lcol)));
#pragma unroll
            for (int j2 = 0; j2 < 2; ++j2) {
                uint32_t bf[4];
                ldsm4(bf, so + 8192 +
                      swz128((uint32_t)((n0 + j2 * 16 + lrow) * 128 + kb2 + lcol)));
#pragma unroll
                for (int mt = 0; mt < 2; ++mt)
#pragma unroll
                    for (int h = 0; h < 2; ++h)
                        mma_f16(acc[mt][j2 * 2 + h], af[mt], bf[h], bf[2 + h]);
            }
        }
        __syncthreads();
    }

    const int grp = lid >> 2, qd = lid & 3;
#pragma unroll
    for (int mt = 0; mt < 2; ++mt)
#pragma unroll
        for (int j = 0; j < 4; ++j)
#pragma unroll
            for (int h = 0; h < 2; ++h) {
                const int row = m_base + m0 + mt * 16 + grp + h * 8;
                const int colg = n0 + (j >> 1) * 16 + (j & 1) * 8 + qd * 2;
                float2 f;
                f.x = acc[mt][j][2 * h]     + g_hbias[colg];
                f.y = acc[mt][j][2 * h + 1] + g_hbias[colg + 1];
                *reinterpret_cast<float2*>(g_heads + (size_t)row * 64 + colg) = f;
            }
}

// ============ fp32 -> fp16 conversion ============
__global__ void __launch_bounds__(256) conv_half(
    const float* __restrict__ s, __half* __restrict__ d, size_t n4)
{
    const size_t i = (size_t)blockIdx.x * 256 + threadIdx.x;
    if (i >= n4) return;
    float4 v = reinterpret_cast<const float4*>(s)[i];
    __half2 p0 = __floats2half2_rn(v.x, v.y);
    __half2 p1 = __floats2half2_rn(v.z, v.w);
    uint2 o; o.x = *reinterpret_cast<uint32_t*>(&p0); o.y = *reinterpret_cast<uint32_t*>(&p1);
    reinterpret_cast<uint2*>(d)[i] = o;
}
__global__ void __launch_bounds__(256) conv_w24(const float* __restrict__ w2,
                                               const float* __restrict__ w4)
{
    const size_t i = (size_t)blockIdx.x * 256 + threadIdx.x;   // over 524288
    const size_t half = 262144;
    const float* s = (i < half) ? w2 : w4;
    const size_t li = (i < half) ? i : i - half;
    float4 v = reinterpret_cast<const float4*>(s)[li];
    __half2 p0 = __floats2half2_rn(v.x, v.y);
    __half2 p1 = __floats2half2_rn(v.z, v.w);
    uint2 o; o.x = *reinterpret_cast<uint32_t*>(&p0); o.y = *reinterpret_cast<uint32_t*>(&p1);
    reinterpret_cast<uint2*>(g_w24)[i] = o;
}

// ============ pack head weights: whead[64][2048], bias[64] ============
__global__ void __launch_bounds__(256) pack_heads(
    const float* __restrict__ w_cls, const float* __restrict__ b_cls,
    const float* __restrict__ w_delta, const float* __restrict__ b_delta,
    const float* __restrict__ w_pos, const float* __restrict__ b_pos,
    const float* __restrict__ w_emb, const float* __restrict__ b_emb)
{
    const int idx = blockIdx.x * 256 + threadIdx.x;   // over 64*2048
    if (idx >= 131072) return;
    const int o = idx >> 11, c = idx & 2047;
    float v = 0.f;
    if (o < 3)       { if (c < 1024)  v = w_cls[o * 1024 + c]; }
    else if (o < 15) { if (c < 1024)  v = w_delta[(o - 3) * 1024 + c]; }
    else if (o < 21) { if (c < 1024)  v = w_pos[(o - 15) * 1024 + c]; }
    else if (o < 53) { if (c >= 1024) v = w_emb[(o - 21) * 1024 + (c - 1024)]; }
    g_whead[idx] = __float2half_rn(v);
    if (idx < 64) {
        float b = 0.f;
        if (idx < 3)       b = b_cls[idx];
        else if (idx < 15) b = b_delta[idx - 3];
        else if (idx < 21) b = b_pos[idx - 15];
        else if (idx < 53) b = b_emb[idx - 21];
        g_hbias[idx] = b;
    }
}

// ============ Postprocess ============
__global__ void __launch_bounds__(128) post_kernel(
    const float* __restrict__ rois, float* __restrict__ out, int out_size)
{
    const int n = blockIdx.x * blockDim.x + threadIdx.x;
    if (n >= 8192) return;
    const float* h = g_heads + (size_t)n * 64;
    float c0 = h[0], c1 = h[1], c2 = h[2];
    float m = fmaxf(c0, fmaxf(c1, c2));
    float e0 = expf(c0 - m), e1 = expf(c1 - m), e2 = expf(c2 - m);
    float inv = 1.f / (e0 + e1 + e2);
    float sc0 = e1 * inv, sc1 = e2 * inv;
    float x1 = rois[n * 5 + 1], y1 = rois[n * 5 + 2];
    float x2 = rois[n * 5 + 3], y2 = rois[n * 5 + 4];
    float bw = x2 - x1, bh = y2 - y1;
    float cx = x1 + 0.5f * bw, cy = y1 + 0.5f * bh;
#pragma unroll
    for (int j = 0; j < 2; ++j) {
        float d0 = h[7 + 4 * j] * 0.1f, d1 = h[8 + 4 * j] * 0.1f;
        float d2 = h[9 + 4 * j] * 0.2f, d3 = h[10 + 4 * j] * 0.2f;
        float p0 = h[17 + 2 * j] * 0.1f, p1 = h[18 + 2 * j] * 0.1f;
        float pcx = d0 * bw + cx, pcy = d1 * bh + cy;
        float pw = expf(d2) * bw, phh = expf(d3) * bh;
        float px = p0 * bw + cx, py = p1 * bh + cy;
        float* ob = out + (size_t)(2 * n + j) * 8;
        ob[0] = pcx - 0.5f * pw;  ob[1] = pcy - 0.5f * phh;
        ob[2] = pcx + 0.5f * pw;  ob[3] = pcy + 0.5f * phh;
        ob[4] = px; ob[5] = py;
        ob[6] = j ? sc1 : sc0;
        ob[7] = (float)(j + 1);
        float* oe = out + 131072 + (size_t)(2 * n + j) * 32;
#pragma unroll
        for (int t = 0; t < 32; ++t) oe[t] = h[21 + t];
    }
    if (n == 0 && out_size > 655360) out[655360] = 2.0f;
}

// ============ launch ============
extern "C" void kernel_launch(void* const* d_in, const int* in_sizes, int n_in,
                              void* d_out, int out_size) {
    const float* pool   = (const float*)d_in[0];
    const float* rois   = (const float*)d_in[1];
    const float* w_fc1  = (const float*)d_in[2];
    const float* b_fc1  = (const float*)d_in[3];
    const float* w_fc2  = (const float*)d_in[4];
    const float* b_fc2  = (const float*)d_in[5];
    const float* w_fc3  = (const float*)d_in[6];
    const float* b_fc3  = (const float*)d_in[7];
    const float* w_fc4  = (const float*)d_in[8];
    const float* b_fc4  = (const float*)d_in[9];
    const float* w_cls  = (const float*)d_in[10];
    const float* b_cls  = (const float*)d_in[11];
    const float* w_delta= (const float*)d_in[12];
    const float* b_delta= (const float*)d_in[13];
    const float* w_pos  = (const float*)d_in[14];
    const float* b_pos  = (const float*)d_in[15];
    const float* w_emb  = (const float*)d_in[16];
    const float* b_emb  = (const float*)d_in[17];
    float* out = (float*)d_out;

    __half *A16, *W13, *W24, *ACT16;
    cudaGetSymbolAddress((void**)&A16,  g_A16);
    cudaGetSymbolAddress((void**)&W13,  g_W13);
    cudaGetSymbolAddress((void**)&W24,  g_w24);
    cudaGetSymbolAddress((void**)&ACT16, g_act16);

    cudaFuncSetAttribute(gemm_kernel<0>, cudaFuncAttributeMaxDynamicSharedMemorySize, SMEM_BYTES);
    cudaFuncSetAttribute(gemm_kernel<1>, cudaFuncAttributeMaxDynamicSharedMemorySize, SMEM_BYTES);
    cudaFuncSetAttribute(heads_gemm,     cudaFuncAttributeMaxDynamicSharedMemorySize, HSMEM);

    // 5 prep launches; gemm1 = launch #6 (ncu -s 5 -c 1 target)
    conv_half<<<100352, 256>>>(pool,  A16,            25690112);                  // L1
    conv_half<<<12544,  256>>>(w_fc1, W13,            3211264);                   // L2
    conv_half<<<12544,  256>>>(w_fc3, W13 + 12845056, 3211264);                   // L3
    conv_w24<<<2048,    256>>>(w_fc2, w_fc4);                                     // L4
    pack_heads<<<512,   256>>>(w_cls, b_cls, w_delta, b_delta,
                               w_pos, b_pos, w_emb, b_emb);                       // L5

    gemm_kernel<0><<<dim3(16, 64), 128, SMEM_BYTES>>>(A16, W13,
                                                      b_fc1, b_fc3, 12544, 12544, 0);  // L6
    gemm_kernel<1><<<dim3(16, 64), 128, SMEM_BYTES>>>(ACT16, W24,
                                                      b_fc2, b_fc4, 1024, 2048, 1);
    heads_gemm<<<128, 128, HSMEM>>>(A16);
    post_kernel<<<64, 128>>>(rois, out, out_size);
}